// round 15
// baseline (speedup 1.0000x reference)
#include <cuda_runtime.h>
#include <math.h>
#include <stdint.h>

#define B_ 8
#define C_ 16
#define S_ 512
#define E_ 256
#define BC_ 128
#define EW  128   // bf16x2 words per row (E/2)
#define SP_ 256   // s-pairs (S/2)

// bf16 scratch: q/k as [s][e-pair]; v TRANSPOSED: [f][s-pair]
__device__ uint32_t g_q[(size_t)BC_ * S_ * EW];
__device__ uint32_t g_k[(size_t)BC_ * S_ * EW];
__device__ uint32_t g_v[(size_t)BC_ * E_ * SP_];

// ---------------------------------------------------------------------------
// helpers
// ---------------------------------------------------------------------------
__device__ __forceinline__ uint32_t pk2(float lo, float hi) {
    uint32_t r;
    asm("cvt.rn.bf16x2.f32 %0, %1, %2;" : "=r"(r) : "f"(hi), "f"(lo));
    return r;
}
__device__ __forceinline__ uint2 pk4(float4 v) {
    uint2 u; u.x = pk2(v.x, v.y); u.y = pk2(v.z, v.w); return u;
}
__device__ __forceinline__ void mma16(float* c, const uint32_t* a, const uint32_t* b) {
    asm volatile(
        "mma.sync.aligned.m16n8k16.row.col.f32.bf16.bf16.f32 "
        "{%0,%1,%2,%3}, {%4,%5,%6,%7}, {%8,%9}, {%0,%1,%2,%3};"
        : "+f"(c[0]), "+f"(c[1]), "+f"(c[2]), "+f"(c[3])
        : "r"(a[0]), "r"(a[1]), "r"(a[2]), "r"(a[3]), "r"(b[0]), "r"(b[1]));
}
__device__ __forceinline__ void ldsm4(uint32_t* r, uint32_t addr) {
    asm volatile("ldmatrix.sync.aligned.m8n8.x4.shared.b16 {%0,%1,%2,%3}, [%4];"
                 : "=r"(r[0]), "=r"(r[1]), "=r"(r[2]), "=r"(r[3]) : "r"(addr));
}
__device__ __forceinline__ void cpa16(uint32_t smem_addr, const void* gptr) {
    asm volatile("cp.async.cg.shared.global [%0], [%1], 16;"
                 :: "r"(smem_addr), "l"(gptr));
}
#define CP_COMMIT() asm volatile("cp.async.commit_group;")
#define CP_WAIT0()  asm volatile("cp.async.wait_group 0;")
#define CP_WAIT1()  asm volatile("cp.async.wait_group 1;")

// ---------------------------------------------------------------------------
// Projection (merged q/k/v): R9 kernel + outer n0 loop so each CTA covers the
// FULL n=256 for its 128-row X slice -> X read from DRAM once, not twice.
// CTA 128x128 per pass, 8 warps (2m x 4n), k-chunk 64. Grid (4, 1, 3*BC).
// ---------------------------------------------------------------------------
#define PA  36
#define PBP 136
#define PT  68

__global__ __launch_bounds__(256, 2) void proj_kernel(
    const float* __restrict__ query, const float* __restrict__ key,
    const float* __restrict__ value,
    const float* __restrict__ wq, const float* __restrict__ wk,
    const float* __restrict__ wv,
    const float* __restrict__ bq, const float* __restrict__ bk,
    const float* __restrict__ bv, float qscale)
{
    __shared__ uint32_t pool[8960];      // sA(4608)+sB(4352); sT(8704) overlay
    uint32_t* sA = pool;
    uint32_t* sB = pool + 4608;
    uint32_t* sT = pool;

    const int zi    = blockIdx.z;
    const int which = zi >> 7;
    const int bc    = zi & (BC_ - 1);
    const int c     = bc % C_;

    const float *X, *W, *bp;
    uint32_t* Yw;
    float scale;
    if (which == 0)      { X = query; W = wq; bp = bq; Yw = g_q + (size_t)bc * S_ * EW; scale = qscale; }
    else if (which == 1) { X = key;   W = wk; bp = bk; Yw = g_k + (size_t)bc * S_ * EW; scale = 1.0f; }
    else                 { X = value; W = wv; bp = bv; Yw = g_v + (size_t)bc * E_ * SP_; scale = 1.0f; }
    X  += (size_t)bc * S_ * E_;
    W  += (size_t)c  * E_ * E_;
    bp += (size_t)c  * E_;

    const int m0 = blockIdx.x * 128;
    const int t  = threadIdx.x;
    const int warp  = t >> 5;
    const int warpm = warp >> 2;
    const int warpn = warp & 3;
    const int lane  = t & 31;
    const int g = lane >> 2;
    const int q = lane & 3;

    const int arow  = (lane & 7) + (((lane >> 3) & 1) << 3);
    const int akadd = (lane >> 4) << 2;
    const uint32_t smbA = (uint32_t)__cvta_generic_to_shared(sA);
    const uint32_t aBase = smbA + (uint32_t)(arow * PA + akadd) * 4u;

    #pragma unroll 1
    for (int n0 = 0; n0 < E_; n0 += 128) {

        float acc[4][4][4];
        #pragma unroll
        for (int i = 0; i < 4; i++)
            #pragma unroll
            for (int j = 0; j < 4; j++)
                #pragma unroll
                for (int r = 0; r < 4; r++) acc[i][j][r] = 0.0f;

        #pragma unroll 1
        for (int k0 = 0; k0 < E_; k0 += 64) {
            #pragma unroll
            for (int i = 0; i < 8; i++) {
                const int idx = t + 256 * i;
                const int row = idx >> 4, c4 = idx & 15;
                *(uint2*)&sA[row * PA + c4 * 2] =
                    pk4(*(const float4*)&X[(size_t)(m0 + row) * E_ + k0 + 4 * c4]);
            }
            #pragma unroll
            for (int i = 0; i < 4; i++) {
                const int idx = t + 256 * i;
                const int kp = idx >> 5, n4 = (idx & 31) * 4;
                const float4 w0 = *(const float4*)&W[(size_t)(k0 + 2 * kp)     * E_ + n0 + n4];
                const float4 w1 = *(const float4*)&W[(size_t)(k0 + 2 * kp + 1) * E_ + n0 + n4];
                uint4 u;
                u.x = pk2(w0.x, w1.x); u.y = pk2(w0.y, w1.y);
                u.z = pk2(w0.z, w1.z); u.w = pk2(w0.w, w1.w);
                *(uint4*)&sB[kp * PBP + n4] = u;
            }
            __syncthreads();

            #pragma unroll
            for (int kkp = 0; kkp < 32; kkp += 8) {
                uint32_t a[4][4], b[4][2];
                #pragma unroll
                for (int mt = 0; mt < 4; mt++)
                    ldsm4(a[mt], aBase + (uint32_t)((warpm * 64 + mt * 16) * PA + kkp) * 4u);
                #pragma unroll
                for (int nt = 0; nt < 4; nt++) {
                    const int n = warpn * 32 + nt * 8 + g;
                    b[nt][0] = sB[(kkp + q) * PBP + n];
                    b[nt][1] = sB[(kkp + q + 4) * PBP + n];
                }
                #pragma unroll
                for (int mt = 0; mt < 4; mt++)
                    #pragma unroll
                    for (int nt = 0; nt < 4; nt++)
                        mma16(acc[mt][nt], a[mt], b[nt]);
            }
            __syncthreads();
        }

        if (which != 2) {
            #pragma unroll
            for (int nt = 0; nt < 4; nt++) {
                const int col = n0 + warpn * 32 + nt * 8 + 2 * q;
                const float b0v = bp[col], b1v = bp[col + 1];
                #pragma unroll
                for (int mt = 0; mt < 4; mt++) {
                    const int row = m0 + warpm * 64 + mt * 16 + g;
                    const float v00 = fmaxf(acc[mt][nt][0] + b0v, 0.0f) * scale;
                    const float v01 = fmaxf(acc[mt][nt][1] + b1v, 0.0f) * scale;
                    const float v10 = fmaxf(acc[mt][nt][2] + b0v, 0.0f) * scale;
                    const float v11 = fmaxf(acc[mt][nt][3] + b1v, 0.0f) * scale;
                    const int cw = (n0 >> 1) + warpn * 16 + nt * 4 + q;
                    Yw[(size_t)row * EW + cw]       = pk2(v00, v01);
                    Yw[(size_t)(row + 8) * EW + cw] = pk2(v10, v11);
                }
            }
        } else {
            #pragma unroll
            for (int nt = 0; nt < 4; nt++) {
                const int col = n0 + warpn * 32 + nt * 8 + 2 * q;
                const float b0v = bp[col], b1v = bp[col + 1];
                #pragma unroll
                for (int mt = 0; mt < 4; mt++) {
                    const float v00 = fmaxf(acc[mt][nt][0] + b0v, 0.0f);
                    const float v01 = fmaxf(acc[mt][nt][1] + b1v, 0.0f);
                    const float v10 = fmaxf(acc[mt][nt][2] + b0v, 0.0f);
                    const float v11 = fmaxf(acc[mt][nt][3] + b1v, 0.0f);
                    const float p00 = __shfl_xor_sync(0xFFFFFFFFu, v00, 4);
                    const float p01 = __shfl_xor_sync(0xFFFFFFFFu, v01, 4);
                    const float p10 = __shfl_xor_sync(0xFFFFFFFFu, v10, 4);
                    const float p11 = __shfl_xor_sync(0xFFFFFFFFu, v11, 4);
                    if ((g & 1) == 0) {
                        const int lcol = warpn * 32 + nt * 8 + 2 * q;
                        const int lsp  = (warpm * 64 + mt * 16 + g) >> 1;
                        sT[lcol * PT + lsp]           = pk2(v00, p00);
                        sT[(lcol + 1) * PT + lsp]     = pk2(v01, p01);
                        sT[lcol * PT + lsp + 4]       = pk2(v10, p10);
                        sT[(lcol + 1) * PT + lsp + 4] = pk2(v11, p11);
                    }
                }
            }
            __syncthreads();
            const int spb = m0 >> 1;
            #pragma unroll
            for (int i = 0; i < 8; i++) {
                const int o = t + 256 * i;
                const int col = o >> 4, j = o & 15;
                *(uint4*)&Yw[(size_t)(n0 + col) * SP_ + spb + j * 4] =
                    *(uint4*)&sT[col * PT + j * 4];
            }
        }
        __syncthreads();   // protect sA/sB (and sT) before next n0 pass
    }
}

// ---------------------------------------------------------------------------
// Attention (exact R9 best): 64 q-rows/CTA, 512 threads (2m x 8n), scores in
// registers, 3-stage cp.async pipelines, ldmatrix operands, 2-round softmax.
// ---------------------------------------------------------------------------
#define PQF 132
#define PKC 20
#define SPP 260
#define PVT 36

#define OFF_SQ 0             // 64*132 = 8448
#define OFF_K  8448          // 3 x 10240 -> ends 39168
#define KSTR   10240
#define OFF_SS 0             // 64*260 = 16640 (overlay)
#define OFF_V  16640         // 3 x 9216 -> ends 44288
#define VSTR   9216
#define OFF_RD 44288         // 1024 floats
#define ATT_WORDS 45312      // 181248 B

__global__ __launch_bounds__(512, 1) void attn_kernel(float* __restrict__ out)
{
    extern __shared__ uint32_t smu[];
    uint32_t* sQ = smu + OFF_SQ;
    uint32_t* sS = smu + OFF_SS;
    float* sRedM = (float*)(smu + OFF_RD);         // [64 rows][8 wn]
    float* sRedS = (float*)(smu + OFF_RD + 512);

    const uint32_t smb = (uint32_t)__cvta_generic_to_shared(smu);

    const int bc = blockIdx.y;
    const int q0 = blockIdx.x * 64;
    const uint32_t* Qw = g_q + (size_t)bc * S_ * EW;
    const uint32_t* Kw = g_k + (size_t)bc * S_ * EW;
    const uint32_t* Vw = g_v + (size_t)bc * E_ * SP_;
    float*          O  = out + (size_t)bc * S_ * E_;

    const int t    = threadIdx.x;
    const int warp = t >> 5;
    const int wm   = warp >> 3;
    const int wn   = warp & 7;
    const int lane = t & 31;
    const int g = lane >> 2;
    const int q = lane & 3;

    const int arow  = (lane & 7) + (((lane >> 3) & 1) << 3);
    const int akadd = (lane >> 4) << 2;
    const int brow  = (lane & 7) + ((lane >> 4) << 3);
    const int bkadd = ((lane >> 3) & 1) << 2;

    const uint32_t aQbase = smb + (uint32_t)(OFF_SQ + (wm * 32 + arow) * PQF + akadd) * 4u;
    const uint32_t aSbase = smb + (uint32_t)(OFF_SS + (wm * 32 + arow) * SPP + akadd) * 4u;
    const uint32_t bKoff  = (uint32_t)(brow * PKC + bkadd) * 4u;
    const uint32_t bVoff  = (uint32_t)(brow * PVT + bkadd) * 4u;

    // ---- issue K chunks 0,1 (3-stage prologue) ---------------------------
    #pragma unroll
    for (int pc = 0; pc < 2; pc++) {
        const uint32_t dst = smb + (uint32_t)(OFF_K + pc * KSTR) * 4u;
        const int ecp = pc * 16;
        #pragma unroll
        for (int i = 0; i < 4; i++) {
            const int o = t + 512 * i;
            const int s = o >> 2, jj = o & 3;
            cpa16(dst + (uint32_t)(s * PKC + jj * 4) * 4u,
                  Kw + (size_t)s * EW + ecp + jj * 4);
        }
        CP_COMMIT();
    }

    // ---- stage whole Q tile (64 x 128 words) -----------------------------
    #pragma unroll
    for (int i = 0; i < 4; i++) {
        const int o = t + 512 * i;
        const int row = o >> 5, j = o & 31;
        *(uint4*)&sQ[row * PQF + j * 4] =
            *(const uint4*)&Qw[(size_t)(q0 + row) * EW + j * 4];
    }

    // ---------------- Phase 1: scores = Q K^T ------------------------------
    float acc[2][8][4];
    #pragma unroll
    for (int mt = 0; mt < 2; mt++)
        #pragma unroll
        for (int nt = 0; nt < 8; nt++)
            #pragma unroll
            for (int r = 0; r < 4; r++) acc[mt][nt][r] = 0.0f;

    #pragma unroll 1
    for (int cch = 0; cch < 8; cch++) {
        if (cch >= 6) { CP_WAIT0(); } else { CP_WAIT1(); }
        __syncthreads();
        if (cch < 6) {
            const uint32_t dst = smb + (uint32_t)(OFF_K + ((cch + 2) % 3) * KSTR) * 4u;
            const int ecp = (cch + 2) * 16;
            #pragma unroll
            for (int i = 0; i < 4; i++) {
                const int o = t + 512 * i;
                const int s = o >> 2, jj = o & 3;
                cpa16(dst + (uint32_t)(s * PKC + jj * 4) * 4u,
                      Kw + (size_t)s * EW + ecp + jj * 4);
            }
            CP_COMMIT();
        }
        const uint32_t bufK = smb + (uint32_t)(OFF_K + (cch % 3) * KSTR) * 4u;
        const int ecp = cch * 16;
        #pragma unroll
        for (int kkp = 0; kkp < 16; kkp += 8) {
            uint32_t a[2][4], b[8][2];
            #pragma unroll
            for (int mt = 0; mt < 2; mt++)
                ldsm4(a[mt], aQbase + (uint32_t)(mt * 16 * PQF + ecp + kkp) * 4u);
            #pragma unroll
            for (int nt2 = 0; nt2 < 8; nt2 += 2) {
                uint32_t r[4];
                ldsm4(r, bufK + (uint32_t)((wn * 64 + nt2 * 8) * PKC + kkp) * 4u + bKoff);
                b[nt2][0] = r[0]; b[nt2][1] = r[1];
                b[nt2 + 1][0] = r[2]; b[nt2 + 1][1] = r[3];
            }
            #pragma unroll
            for (int mt = 0; mt < 2; mt++)
                #pragma unroll
                for (int nt = 0; nt < 8; nt++)
                    mma16(acc[mt][nt], a[mt], b[nt]);
        }
    }

    // ---------------- Softmax (fp32 on fragments) --------------------------
    float rmax[4], rinv[4];
    #pragma unroll
    for (int mt = 0; mt < 2; mt++)
        #pragma unroll
        for (int h = 0; h < 2; h++) {
            float m = -1e30f;
            #pragma unroll
            for (int nt = 0; nt < 8; nt++) {
                m = fmaxf(m, acc[mt][nt][2 * h]);
                m = fmaxf(m, acc[mt][nt][2 * h + 1]);
            }
            m = fmaxf(m, __shfl_xor_sync(0xFFFFFFFFu, m, 1));
            m = fmaxf(m, __shfl_xor_sync(0xFFFFFFFFu, m, 2));
            rmax[mt * 2 + h] = m;
        }
    __syncthreads();   // all phase-1 K/Q smem reads done — overlays now safe

    // ---- issue V chunks 0,1,2 (overlap the whole softmax) -----------------
    #pragma unroll
    for (int pc = 0; pc < 3; pc++) {
        const uint32_t dst = smb + (uint32_t)(OFF_V + pc * VSTR) * 4u;
        const int spb = pc * 32;
        #pragma unroll
        for (int i = 0; i < 4; i++) {
            const int o = t + 512 * i;
            const int f = o >> 3, jj = o & 7;
            cpa16(dst + (uint32_t)(f * PVT + jj * 4) * 4u,
                  Vw + (size_t)f * SP_ + spb + jj * 4);
        }
        CP_COMMIT();
    }

    if (q == 0) {
        #pragma unroll
        for (int mt = 0; mt < 2; mt++)
            #pragma unroll
            for (int h = 0; h < 2; h++)
                sRedM[(wm * 32 + mt * 16 + h * 8 + g) * 8 + wn] = rmax[mt * 2 + h];
    }
    __syncthreads();
    #pragma unroll
    for (int s = 0; s < 4; s++) {
        const int row = wm * 32 + (s >> 1) * 16 + (s & 1) * 8 + g;
        float m = sRedM[row * 8];
        #pragma unroll
        for (int w = 1; w < 8; w++) m = fmaxf(m, sRedM[row * 8 + w]);
        rmax[s] = m;
    }

    #pragma unroll
    for (int mt = 0; mt < 2; mt++)
        #pragma unroll
        for (int h = 0; h < 2; h++) {
            float s = 0.0f;
            #pragma unroll
            for (int nt = 0; nt < 8; nt++) {
                float p0 = __expf(acc[mt][nt][2 * h]     - rmax[mt * 2 + h]);
                float p1 = __expf(acc[mt][nt][2 * h + 1] - rmax[mt * 2 + h]);
                acc[mt][nt][2 * h]     = p0;
                acc[mt][nt][2 * h + 1] = p1;
                s += p0 + p1;
            }
            s += __shfl_xor_sync(0xFFFFFFFFu, s, 1);
            s += __shfl_xor_sync(0xFFFFFFFFu, s, 2);
            if (q == 0) sRedS[(wm * 32 + mt * 16 + h * 8 + g) * 8 + wn] = s;
        }
    __syncthreads();
    #pragma unroll
    for (int s = 0; s < 4; s++) {
        const int row = wm * 32 + (s >> 1) * 16 + (s & 1) * 8 + g;
        float sum = 0.0f;
        #pragma unroll
        for (int w = 0; w < 8; w++) sum += sRedS[row * 8 + w];
        rinv[s] = 1.0f / sum;
    }

    // Store unnormalized P (bf16 pairs) to sS
    #pragma unroll
    for (int mt = 0; mt < 2; mt++)
        #pragma unroll
        for (int h = 0; h < 2; h++) {
            const int row = wm * 32 + mt * 16 + h * 8 + g;
            #pragma unroll
            for (int nt = 0; nt < 8; nt++)
                sS[row * SPP + wn * 32 + nt * 4 + q] =
                    pk2(acc[mt][nt][2 * h], acc[mt][nt][2 * h + 1]);
        }

    // ---------------- Phase 2: out = P V -----------------------------------
    float acc2[2][4][4];
    #pragma unroll
    for (int mt = 0; mt < 2; mt++)
        #pragma unroll
        for (int nt = 0; nt < 4; nt++)
            #pragma unroll
            for (int r = 0; r < 4; r++) acc2[mt][nt][r] = 0.0f;

    #pragma unroll 1
    for (int cch = 0; cch < 8; cch++) {
        if (cch >= 6) { CP_WAIT0(); } else { CP_WAIT1(); }
        __syncthreads();           // V chunk ready + (first iter) P visible
        if (cch < 6) {
            const uint32_t dst = smb + (uint32_t)(OFF_V + ((cch + 2) % 3) * VSTR) * 4u;
            const int spb = (cch + 2) * 32;
            #pragma unroll
            for (int i = 0; i < 4; i++) {
                const int o = t + 512 * i;
                const int f = o >> 3, jj = o & 7;
                cpa16(dst + (uint32_t)(f * PVT + jj * 4) * 4u,
                      Vw + (size_t)f * SP_ + spb + jj * 4);
            }
            CP_COMMIT();
        }
        const uint32_t bufV = smb + (uint32_t)(OFF_V + (cch % 3) * VSTR) * 4u;
        const int ktp = cch * 32;
        #pragma unroll
        for (int kkp = 0; kkp < 32; kkp += 8) {
            uint32_t a[2][4], b[4][2];
            #pragma unroll
            for (int mt = 0; mt < 2; mt++)
                ldsm4(a[mt], aSbase + (uint32_t)(mt * 16 * SPP + ktp + kkp) * 4u);
            #pragma unroll
            for (int nt2 = 0; nt2 < 4; nt2 += 2) {
                uint32_t r[4];
                ldsm4(r, bufV + (uint32_t)((wn * 32 + nt2 * 8) * PVT + kkp) * 4u + bVoff);
                b[nt2][0] = r[0]; b[nt2][1] = r[1];
                b[nt2 + 1][0] = r[2]; b[nt2 + 1][1] = r[3];
            }
            #pragma unroll
            for (int mt = 0; mt < 2; mt++)
                #pragma unroll
                for (int nt = 0; nt < 4; nt++)
                    mma16(acc2[mt][nt], a[mt], b[nt]);
        }
    }

    // Epilogue: normalize + store fp32
    #pragma unroll
    for (int mt = 0; mt < 2; mt++)
        #pragma unroll
        for (int h = 0; h < 2; h++) {
            const int row = q0 + wm * 32 + mt * 16 + h * 8 + g;
            const float inv = rinv[mt * 2 + h];
            #pragma unroll
            for (int nt = 0; nt < 4; nt++) {
                const int col = wn * 32 + nt * 8 + 2 * q;
                float2 v;
                v.x = acc2[mt][nt][2 * h]     * inv;
                v.y = acc2[mt][nt][2 * h + 1] * inv;
                *(float2*)&O[(size_t)row * E_ + col] = v;
            }
        }
}

// ---------------------------------------------------------------------------
extern "C" void kernel_launch(void* const* d_in, const int* in_sizes, int n_in,
                              void* d_out, int out_size)
{
    const float* query = (const float*)d_in[0];
    const float* key   = (const float*)d_in[1];
    const float* value = (const float*)d_in[2];
    const float* wq    = (const float*)d_in[3];
    const float* wk    = (const float*)d_in[4];
    const float* wv    = (const float*)d_in[5];
    const float* bq    = (const float*)d_in[6];
    const float* bk    = (const float*)d_in[7];
    const float* bv    = (const float*)d_in[8];
    float* out = (float*)d_out;

    const float qscale = 1.0f / sqrtf((float)E_);

    dim3 pgrid(S_ / 128, 1, 3 * BC_);
    proj_kernel<<<pgrid, 256>>>(query, key, value, wq, wk, wv, bq, bk, bv, qscale);

    const size_t smem = (size_t)ATT_WORDS * sizeof(uint32_t);
    cudaFuncSetAttribute(attn_kernel, cudaFuncAttributeMaxDynamicSharedMemorySize,
                         (int)smem);
    attn_kernel<<<dim3(S_ / 64, BC_), 512, smem>>>(out);
}

// round 16
// speedup vs baseline: 1.0615x; 1.0615x over previous
#include <cuda_runtime.h>
#include <math.h>
#include <stdint.h>

#define B_ 8
#define C_ 16
#define S_ 512
#define E_ 256
#define BC_ 128
#define EW  128   // bf16x2 words per row (E/2)
#define SP_ 256   // s-pairs (S/2)

// bf16 scratch: q/k as [s][e-pair]; v TRANSPOSED: [f][s-pair]
__device__ uint32_t g_q[(size_t)BC_ * S_ * EW];
__device__ uint32_t g_k[(size_t)BC_ * S_ * EW];
__device__ uint32_t g_v[(size_t)BC_ * E_ * SP_];

// ---------------------------------------------------------------------------
// helpers
// ---------------------------------------------------------------------------
__device__ __forceinline__ uint32_t pk2(float lo, float hi) {
    uint32_t r;
    asm("cvt.rn.bf16x2.f32 %0, %1, %2;" : "=r"(r) : "f"(hi), "f"(lo));
    return r;
}
__device__ __forceinline__ uint2 pk4(float4 v) {
    uint2 u; u.x = pk2(v.x, v.y); u.y = pk2(v.z, v.w); return u;
}
__device__ __forceinline__ void mma16(float* c, const uint32_t* a, const uint32_t* b) {
    asm volatile(
        "mma.sync.aligned.m16n8k16.row.col.f32.bf16.bf16.f32 "
        "{%0,%1,%2,%3}, {%4,%5,%6,%7}, {%8,%9}, {%0,%1,%2,%3};"
        : "+f"(c[0]), "+f"(c[1]), "+f"(c[2]), "+f"(c[3])
        : "r"(a[0]), "r"(a[1]), "r"(a[2]), "r"(a[3]), "r"(b[0]), "r"(b[1]));
}
__device__ __forceinline__ void ldsm4(uint32_t* r, uint32_t addr) {
    asm volatile("ldmatrix.sync.aligned.m8n8.x4.shared.b16 {%0,%1,%2,%3}, [%4];"
                 : "=r"(r[0]), "=r"(r[1]), "=r"(r[2]), "=r"(r[3]) : "r"(addr));
}
__device__ __forceinline__ void cpa16(uint32_t smem_addr, const void* gptr) {
    asm volatile("cp.async.cg.shared.global [%0], [%1], 16;"
                 :: "r"(smem_addr), "l"(gptr));
}
#define CP_COMMIT() asm volatile("cp.async.commit_group;")
#define CP_WAIT0()  asm volatile("cp.async.wait_group 0;")

// ---------------------------------------------------------------------------
// Projection (merged q/k/v) — EXACT R9 best (141 us). CTA 128x128, 8 warps
// (2m x 4n), k-chunk 64. Grid (4, 2, 3*BC).
// ---------------------------------------------------------------------------
#define PA  36
#define PBP 136
#define PT  68

__global__ __launch_bounds__(256) void proj_kernel(
    const float* __restrict__ query, const float* __restrict__ key,
    const float* __restrict__ value,
    const float* __restrict__ wq, const float* __restrict__ wk,
    const float* __restrict__ wv,
    const float* __restrict__ bq, const float* __restrict__ bk,
    const float* __restrict__ bv, float qscale)
{
    __shared__ uint32_t pool[8960];
    uint32_t* sA = pool;
    uint32_t* sB = pool + 4608;
    uint32_t* sT = pool;

    const int zi    = blockIdx.z;
    const int which = zi >> 7;
    const int bc    = zi & (BC_ - 1);
    const int c     = bc % C_;

    const float *X, *W, *bp;
    uint32_t* Yw;
    float scale;
    if (which == 0)      { X = query; W = wq; bp = bq; Yw = g_q + (size_t)bc * S_ * EW; scale = qscale; }
    else if (which == 1) { X = key;   W = wk; bp = bk; Yw = g_k + (size_t)bc * S_ * EW; scale = 1.0f; }
    else                 { X = value; W = wv; bp = bv; Yw = g_v + (size_t)bc * E_ * SP_; scale = 1.0f; }
    X  += (size_t)bc * S_ * E_;
    W  += (size_t)c  * E_ * E_;
    bp += (size_t)c  * E_;

    const int m0 = blockIdx.x * 128;
    const int n0 = blockIdx.y * 128;
    const int t  = threadIdx.x;
    const int warp  = t >> 5;
    const int warpm = warp >> 2;
    const int warpn = warp & 3;
    const int lane  = t & 31;
    const int g = lane >> 2;
    const int q = lane & 3;

    const int arow  = (lane & 7) + (((lane >> 3) & 1) << 3);
    const int akadd = (lane >> 4) << 2;
    const uint32_t smbA = (uint32_t)__cvta_generic_to_shared(sA);
    const uint32_t aBase = smbA + (uint32_t)(arow * PA + akadd) * 4u;

    float acc[4][4][4];
    #pragma unroll
    for (int i = 0; i < 4; i++)
        #pragma unroll
        for (int j = 0; j < 4; j++)
            #pragma unroll
            for (int r = 0; r < 4; r++) acc[i][j][r] = 0.0f;

    for (int k0 = 0; k0 < E_; k0 += 64) {
        #pragma unroll
        for (int i = 0; i < 8; i++) {
            const int idx = t + 256 * i;
            const int row = idx >> 4, c4 = idx & 15;
            *(uint2*)&sA[row * PA + c4 * 2] =
                pk4(*(const float4*)&X[(size_t)(m0 + row) * E_ + k0 + 4 * c4]);
        }
        #pragma unroll
        for (int i = 0; i < 4; i++) {
            const int idx = t + 256 * i;
            const int kp = idx >> 5, n4 = (idx & 31) * 4;
            const float4 w0 = *(const float4*)&W[(size_t)(k0 + 2 * kp)     * E_ + n0 + n4];
            const float4 w1 = *(const float4*)&W[(size_t)(k0 + 2 * kp + 1) * E_ + n0 + n4];
            uint4 u;
            u.x = pk2(w0.x, w1.x); u.y = pk2(w0.y, w1.y);
            u.z = pk2(w0.z, w1.z); u.w = pk2(w0.w, w1.w);
            *(uint4*)&sB[kp * PBP + n4] = u;
        }
        __syncthreads();

        #pragma unroll
        for (int kkp = 0; kkp < 32; kkp += 8) {
            uint32_t a[4][4], b[4][2];
            #pragma unroll
            for (int mt = 0; mt < 4; mt++)
                ldsm4(a[mt], aBase + (uint32_t)((warpm * 64 + mt * 16) * PA + kkp) * 4u);
            #pragma unroll
            for (int nt = 0; nt < 4; nt++) {
                const int n = warpn * 32 + nt * 8 + g;
                b[nt][0] = sB[(kkp + q) * PBP + n];
                b[nt][1] = sB[(kkp + q + 4) * PBP + n];
            }
            #pragma unroll
            for (int mt = 0; mt < 4; mt++)
                #pragma unroll
                for (int nt = 0; nt < 4; nt++)
                    mma16(acc[mt][nt], a[mt], b[nt]);
        }
        __syncthreads();
    }

    if (which != 2) {
        #pragma unroll
        for (int nt = 0; nt < 4; nt++) {
            const int col = n0 + warpn * 32 + nt * 8 + 2 * q;
            const float b0v = bp[col], b1v = bp[col + 1];
            #pragma unroll
            for (int mt = 0; mt < 4; mt++) {
                const int row = m0 + warpm * 64 + mt * 16 + g;
                const float v00 = fmaxf(acc[mt][nt][0] + b0v, 0.0f) * scale;
                const float v01 = fmaxf(acc[mt][nt][1] + b1v, 0.0f) * scale;
                const float v10 = fmaxf(acc[mt][nt][2] + b0v, 0.0f) * scale;
                const float v11 = fmaxf(acc[mt][nt][3] + b1v, 0.0f) * scale;
                const int cw = (n0 >> 1) + warpn * 16 + nt * 4 + q;
                Yw[(size_t)row * EW + cw]       = pk2(v00, v01);
                Yw[(size_t)(row + 8) * EW + cw] = pk2(v10, v11);
            }
        }
    } else {
        #pragma unroll
        for (int nt = 0; nt < 4; nt++) {
            const int col = n0 + warpn * 32 + nt * 8 + 2 * q;
            const float b0v = bp[col], b1v = bp[col + 1];
            #pragma unroll
            for (int mt = 0; mt < 4; mt++) {
                const float v00 = fmaxf(acc[mt][nt][0] + b0v, 0.0f);
                const float v01 = fmaxf(acc[mt][nt][1] + b1v, 0.0f);
                const float v10 = fmaxf(acc[mt][nt][2] + b0v, 0.0f);
                const float v11 = fmaxf(acc[mt][nt][3] + b1v, 0.0f);
                const float p00 = __shfl_xor_sync(0xFFFFFFFFu, v00, 4);
                const float p01 = __shfl_xor_sync(0xFFFFFFFFu, v01, 4);
                const float p10 = __shfl_xor_sync(0xFFFFFFFFu, v10, 4);
                const float p11 = __shfl_xor_sync(0xFFFFFFFFu, v11, 4);
                if ((g & 1) == 0) {
                    const int lcol = warpn * 32 + nt * 8 + 2 * q;
                    const int lsp  = (warpm * 64 + mt * 16 + g) >> 1;
                    sT[lcol * PT + lsp]           = pk2(v00, p00);
                    sT[(lcol + 1) * PT + lsp]     = pk2(v01, p01);
                    sT[lcol * PT + lsp + 4]       = pk2(v10, p10);
                    sT[(lcol + 1) * PT + lsp + 4] = pk2(v11, p11);
                }
            }
        }
        __syncthreads();
        const int spb = m0 >> 1;
        #pragma unroll
        for (int i = 0; i < 8; i++) {
            const int o = t + 256 * i;
            const int col = o >> 4, j = o & 15;
            *(uint4*)&Yw[(size_t)(n0 + col) * SP_ + spb + j * 4] =
                *(uint4*)&sT[col * PT + j * 4];
        }
    }
}

// ---------------------------------------------------------------------------
// Attention v6: R9 structure, but 4 double-size chunks per phase (half the
// barriers), 2-stage buffering. 64 q-rows/CTA, 512 threads (2m x 8n).
// ---------------------------------------------------------------------------
#define PQF 132   // sQ pitch
#define PKC 36    // sK chunk pitch (32 words + 4)
#define SPP 260   // sS pitch
#define PVT 68    // sV chunk pitch (64 words + 4)

#define OFF_SQ 0             // 64*132 = 8448
#define OFF_K  8448          // 2 x 18432 -> ends 45312
#define KSTR   18432
#define OFF_SS 0             // 64*260 = 16640 (overlay)
#define OFF_V  16640         // 2 x 17408 -> ends 51456
#define VSTR   17408
#define OFF_RD 51456         // 1024 floats
#define ATT_WORDS 52480      // 209920 B

__global__ __launch_bounds__(512, 1) void attn_kernel(float* __restrict__ out)
{
    extern __shared__ uint32_t smu[];
    uint32_t* sQ = smu + OFF_SQ;
    uint32_t* sS = smu + OFF_SS;
    float* sRedM = (float*)(smu + OFF_RD);         // [64 rows][8 wn]
    float* sRedS = (float*)(smu + OFF_RD + 512);

    const uint32_t smb = (uint32_t)__cvta_generic_to_shared(smu);

    const int bc = blockIdx.y;
    const int q0 = blockIdx.x * 64;
    const uint32_t* Qw = g_q + (size_t)bc * S_ * EW;
    const uint32_t* Kw = g_k + (size_t)bc * S_ * EW;
    const uint32_t* Vw = g_v + (size_t)bc * E_ * SP_;
    float*          O  = out + (size_t)bc * S_ * E_;

    const int t    = threadIdx.x;
    const int warp = t >> 5;
    const int wm   = warp >> 3;
    const int wn   = warp & 7;
    const int lane = t & 31;
    const int g = lane >> 2;
    const int q = lane & 3;

    const int arow  = (lane & 7) + (((lane >> 3) & 1) << 3);
    const int akadd = (lane >> 4) << 2;
    const int brow  = (lane & 7) + ((lane >> 4) << 3);
    const int bkadd = ((lane >> 3) & 1) << 2;

    const uint32_t aQbase = smb + (uint32_t)(OFF_SQ + (wm * 32 + arow) * PQF + akadd) * 4u;
    const uint32_t aSbase = smb + (uint32_t)(OFF_SS + (wm * 32 + arow) * SPP + akadd) * 4u;
    const uint32_t bKoff  = (uint32_t)(brow * PKC + bkadd) * 4u;
    const uint32_t bVoff  = (uint32_t)(brow * PVT + bkadd) * 4u;

    // ---- issue K chunk 0 (512 rows x 32 words) ---------------------------
    {
        #pragma unroll
        for (int i = 0; i < 8; i++) {
            const int o = t + 512 * i;
            const int s = o >> 3, jj = o & 7;
            cpa16(smb + (uint32_t)(OFF_K + s * PKC + jj * 4) * 4u,
                  Kw + (size_t)s * EW + jj * 4);
        }
        CP_COMMIT();
    }

    // ---- stage whole Q tile (64 x 128 words) -----------------------------
    #pragma unroll
    for (int i = 0; i < 4; i++) {
        const int o = t + 512 * i;
        const int row = o >> 5, j = o & 31;
        *(uint4*)&sQ[row * PQF + j * 4] =
            *(const uint4*)&Qw[(size_t)(q0 + row) * EW + j * 4];
    }

    // ---------------- Phase 1: scores = Q K^T (4 chunks of 64 e) ----------
    float acc[2][8][4];
    #pragma unroll
    for (int mt = 0; mt < 2; mt++)
        #pragma unroll
        for (int nt = 0; nt < 8; nt++)
            #pragma unroll
            for (int r = 0; r < 4; r++) acc[mt][nt][r] = 0.0f;

    #pragma unroll 1
    for (int cch = 0; cch < 4; cch++) {
        CP_WAIT0();
        __syncthreads();
        if (cch < 3) {
            const uint32_t dst = smb + (uint32_t)(OFF_K + ((cch + 1) & 1) * KSTR) * 4u;
            const int ecp = (cch + 1) * 32;
            #pragma unroll
            for (int i = 0; i < 8; i++) {
                const int o = t + 512 * i;
                const int s = o >> 3, jj = o & 7;
                cpa16(dst + (uint32_t)(s * PKC + jj * 4) * 4u,
                      Kw + (size_t)s * EW + ecp + jj * 4);
            }
            CP_COMMIT();
        }
        const uint32_t bufK = smb + (uint32_t)(OFF_K + (cch & 1) * KSTR) * 4u;
        const int ecp = cch * 32;
        #pragma unroll
        for (int kkp = 0; kkp < 32; kkp += 8) {
            uint32_t a[2][4], b[8][2];
            #pragma unroll
            for (int mt = 0; mt < 2; mt++)
                ldsm4(a[mt], aQbase + (uint32_t)(mt * 16 * PQF + ecp + kkp) * 4u);
            #pragma unroll
            for (int nt2 = 0; nt2 < 8; nt2 += 2) {
                uint32_t r[4];
                ldsm4(r, bufK + (uint32_t)((wn * 64 + nt2 * 8) * PKC + kkp) * 4u + bKoff);
                b[nt2][0] = r[0]; b[nt2][1] = r[1];
                b[nt2 + 1][0] = r[2]; b[nt2 + 1][1] = r[3];
            }
            #pragma unroll
            for (int mt = 0; mt < 2; mt++)
                #pragma unroll
                for (int nt = 0; nt < 8; nt++)
                    mma16(acc[mt][nt], a[mt], b[nt]);
        }
    }

    // ---------------- Softmax (fp32 on fragments, R9 2-round) --------------
    float rmax[4], rinv[4];
    #pragma unroll
    for (int mt = 0; mt < 2; mt++)
        #pragma unroll
        for (int h = 0; h < 2; h++) {
            float m = -1e30f;
            #pragma unroll
            for (int nt = 0; nt < 8; nt++) {
                m = fmaxf(m, acc[mt][nt][2 * h]);
                m = fmaxf(m, acc[mt][nt][2 * h + 1]);
            }
            m = fmaxf(m, __shfl_xor_sync(0xFFFFFFFFu, m, 1));
            m = fmaxf(m, __shfl_xor_sync(0xFFFFFFFFu, m, 2));
            rmax[mt * 2 + h] = m;
        }
    __syncthreads();   // all phase-1 K/Q smem reads done — overlays now safe

    // ---- issue V chunk 0 (256 f x 64 sp-words) — overlaps softmax --------
    {
        #pragma unroll
        for (int i = 0; i < 8; i++) {
            const int o = t + 512 * i;
            const int f = o >> 4, jj = o & 15;
            cpa16(smb + (uint32_t)(OFF_V + f * PVT + jj * 4) * 4u,
                  Vw + (size_t)f * SP_ + jj * 4);
        }
        CP_COMMIT();
    }

    if (q == 0) {
        #pragma unroll
        for (int mt = 0; mt < 2; mt++)
            #pragma unroll
            for (int h = 0; h < 2; h++)
                sRedM[(wm * 32 + mt * 16 + h * 8 + g) * 8 + wn] = rmax[mt * 2 + h];
    }
    __syncthreads();
    #pragma unroll
    for (int s = 0; s < 4; s++) {
        const int row = wm * 32 + (s >> 1) * 16 + (s & 1) * 8 + g;
        float m = sRedM[row * 8];
        #pragma unroll
        for (int w = 1; w < 8; w++) m = fmaxf(m, sRedM[row * 8 + w]);
        rmax[s] = m;
    }

    #pragma unroll
    for (int mt = 0; mt < 2; mt++)
        #pragma unroll
        for (int h = 0; h < 2; h++) {
            float s = 0.0f;
            #pragma unroll
            for (int nt = 0; nt < 8; nt++) {
                float p0 = __expf(acc[mt][nt][2 * h]     - rmax[mt * 2 + h]);
                float p1 = __expf(acc[mt][nt][2 * h + 1] - rmax[mt * 2 + h]);
                acc[mt][nt][2 * h]     = p0;
                acc[mt][nt][2 * h + 1] = p1;
                s += p0 + p1;
            }
            s += __shfl_xor_sync(0xFFFFFFFFu, s, 1);
            s += __shfl_xor_sync(0xFFFFFFFFu, s, 2);
            if (q == 0) sRedS[(wm * 32 + mt * 16 + h * 8 + g) * 8 + wn] = s;
        }
    __syncthreads();
    #pragma unroll
    for (int s = 0; s < 4; s++) {
        const int row = wm * 32 + (s >> 1) * 16 + (s & 1) * 8 + g;
        float sum = 0.0f;
        #pragma unroll
        for (int w = 0; w < 8; w++) sum += sRedS[row * 8 + w];
        rinv[s] = 1.0f / sum;
    }

    // Store unnormalized P (bf16 pairs) to sS
    #pragma unroll
    for (int mt = 0; mt < 2; mt++)
        #pragma unroll
        for (int h = 0; h < 2; h++) {
            const int row = wm * 32 + mt * 16 + h * 8 + g;
            #pragma unroll
            for (int nt = 0; nt < 8; nt++)
                sS[row * SPP + wn * 32 + nt * 4 + q] =
                    pk2(acc[mt][nt][2 * h], acc[mt][nt][2 * h + 1]);
        }

    // ---------------- Phase 2: out = P V (4 chunks of 128 s) ---------------
    float acc2[2][4][4];
    #pragma unroll
    for (int mt = 0; mt < 2; mt++)
        #pragma unroll
        for (int nt = 0; nt < 4; nt++)
            #pragma unroll
            for (int r = 0; r < 4; r++) acc2[mt][nt][r] = 0.0f;

    #pragma unroll 1
    for (int cch = 0; cch < 4; cch++) {
        CP_WAIT0();
        __syncthreads();           // V chunk ready + (first iter) P visible
        if (cch < 3) {
            const uint32_t dst = smb + (uint32_t)(OFF_V + ((cch + 1) & 1) * VSTR) * 4u;
            const int spb = (cch + 1) * 64;
            #pragma unroll
            for (int i = 0; i < 8; i++) {
                const int o = t + 512 * i;
                const int f = o >> 4, jj = o & 15;
                cpa16(dst + (uint32_t)(f * PVT + jj * 4) * 4u,
                      Vw + (size_t)f * SP_ + spb + jj * 4);
            }
            CP_COMMIT();
        }
        const uint32_t bufV = smb + (uint32_t)(OFF_V + (cch & 1) * VSTR) * 4u;
        const int ktp = cch * 64;
        #pragma unroll
        for (int kkp = 0; kkp < 64; kkp += 8) {
            uint32_t a[2][4], b[4][2];
            #pragma unroll
            for (int mt = 0; mt < 2; mt++)
                ldsm4(a[mt], aSbase + (uint32_t)(mt * 16 * SPP + ktp + kkp) * 4u);
            #pragma unroll
            for (int nt2 = 0; nt2 < 4; nt2 += 2) {
                uint32_t r[4];
                ldsm4(r, bufV + (uint32_t)((wn * 32 + nt2 * 8) * PVT + kkp) * 4u + bVoff);
                b[nt2][0] = r[0]; b[nt2][1] = r[1];
                b[nt2 + 1][0] = r[2]; b[nt2 + 1][1] = r[3];
            }
            #pragma unroll
            for (int mt = 0; mt < 2; mt++)
                #pragma unroll
                for (int nt = 0; nt < 4; nt++)
                    mma16(acc2[mt][nt], a[mt], b[nt]);
        }
    }

    // Epilogue: normalize + store fp32
    #pragma unroll
    for (int mt = 0; mt < 2; mt++)
        #pragma unroll
        for (int h = 0; h < 2; h++) {
            const int row = q0 + wm * 32 + mt * 16 + h * 8 + g;
            const float inv = rinv[mt * 2 + h];
            #pragma unroll
            for (int nt = 0; nt < 4; nt++) {
                const int col = wn * 32 + nt * 8 + 2 * q;
                float2 v;
                v.x = acc2[mt][nt][2 * h]     * inv;
                v.y = acc2[mt][nt][2 * h + 1] * inv;
                *(float2*)&O[(size_t)row * E_ + col] = v;
            }
        }
}

// ---------------------------------------------------------------------------
extern "C" void kernel_launch(void* const* d_in, const int* in_sizes, int n_in,
                              void* d_out, int out_size)
{
    const float* query = (const float*)d_in[0];
    const float* key   = (const float*)d_in[1];
    const float* value = (const float*)d_in[2];
    const float* wq    = (const float*)d_in[3];
    const float* wk    = (const float*)d_in[4];
    const float* wv    = (const float*)d_in[5];
    const float* bq    = (const float*)d_in[6];
    const float* bk    = (const float*)d_in[7];
    const float* bv    = (const float*)d_in[8];
    float* out = (float*)d_out;

    const float qscale = 1.0f / sqrtf((float)E_);

    dim3 pgrid(S_ / 128, E_ / 128, 3 * BC_);
    proj_kernel<<<pgrid, 256>>>(query, key, value, wq, wk, wv, bq, bk, bv, qscale);

    const size_t smem = (size_t)ATT_WORDS * sizeof(uint32_t);
    cudaFuncSetAttribute(attn_kernel, cudaFuncAttributeMaxDynamicSharedMemorySize,
                         (int)smem);
    attn_kernel<<<dim3(S_ / 64, BC_), 512, smem>>>(out);
}

// round 17
// speedup vs baseline: 1.0637x; 1.0022x over previous
#include <cuda_runtime.h>
#include <math.h>
#include <stdint.h>

#define B_ 8
#define C_ 16
#define S_ 512
#define E_ 256
#define BC_ 128
#define EW  128   // bf16x2 words per row (E/2)
#define SP_ 256   // s-pairs (S/2)

// bf16 scratch: q/k as [s][e-pair]; v TRANSPOSED: [f][s-pair]
__device__ uint32_t g_q[(size_t)BC_ * S_ * EW];
__device__ uint32_t g_k[(size_t)BC_ * S_ * EW];
__device__ uint32_t g_v[(size_t)BC_ * E_ * SP_];

// ---------------------------------------------------------------------------
// helpers
// ---------------------------------------------------------------------------
__device__ __forceinline__ uint32_t pk2(float lo, float hi) {
    uint32_t r;
    asm("cvt.rn.bf16x2.f32 %0, %1, %2;" : "=r"(r) : "f"(hi), "f"(lo));
    return r;
}
__device__ __forceinline__ uint2 pk4(float4 v) {
    uint2 u; u.x = pk2(v.x, v.y); u.y = pk2(v.z, v.w); return u;
}
__device__ __forceinline__ void mma16(float* c, const uint32_t* a, const uint32_t* b) {
    asm volatile(
        "mma.sync.aligned.m16n8k16.row.col.f32.bf16.bf16.f32 "
        "{%0,%1,%2,%3}, {%4,%5,%6,%7}, {%8,%9}, {%0,%1,%2,%3};"
        : "+f"(c[0]), "+f"(c[1]), "+f"(c[2]), "+f"(c[3])
        : "r"(a[0]), "r"(a[1]), "r"(a[2]), "r"(a[3]), "r"(b[0]), "r"(b[1]));
}
__device__ __forceinline__ void ldsm4(uint32_t* r, uint32_t addr) {
    asm volatile("ldmatrix.sync.aligned.m8n8.x4.shared.b16 {%0,%1,%2,%3}, [%4];"
                 : "=r"(r[0]), "=r"(r[1]), "=r"(r[2]), "=r"(r[3]) : "r"(addr));
}
__device__ __forceinline__ void cpa16(uint32_t smem_addr, const void* gptr) {
    asm volatile("cp.async.cg.shared.global [%0], [%1], 16;"
                 :: "r"(smem_addr), "l"(gptr));
}
#define CP_COMMIT() asm volatile("cp.async.commit_group;")
#define CP_WAIT0()  asm volatile("cp.async.wait_group 0;")

// ---------------------------------------------------------------------------
// Projection (merged q/k/v): R16 structure with k-chunk 128 (4 -> 2 chunks,
// half the barriers). CTA 128x128, 8 warps (2m x 4n). Dynamic smem 68 KB,
// 2 CTAs/SM. Grid (4, 2, 3*BC).
// ---------------------------------------------------------------------------
#define PA2 68     // sA pitch (64 kp + 4 pad), 68 % 32 == 4 -> A-frag clean
#define PBP 136    // sB pitch, 136 % 32 == 8 -> B-frag clean
#define PT  68     // V-transpose buffer pitch (overlay on sA)
#define PJ_A_WORDS 8704            // 128 * 68
#define PJ_WORDS  (PJ_A_WORDS + 64 * PBP)   // + 8704 = 17408 words (69632 B)

__global__ __launch_bounds__(256, 2) void proj_kernel(
    const float* __restrict__ query, const float* __restrict__ key,
    const float* __restrict__ value,
    const float* __restrict__ wq, const float* __restrict__ wk,
    const float* __restrict__ wv,
    const float* __restrict__ bq, const float* __restrict__ bk,
    const float* __restrict__ bv, float qscale)
{
    extern __shared__ uint32_t pool[];
    uint32_t* sA = pool;
    uint32_t* sB = pool + PJ_A_WORDS;
    uint32_t* sT = pool;                 // overlay (epilogue only)

    const int zi    = blockIdx.z;
    const int which = zi >> 7;
    const int bc    = zi & (BC_ - 1);
    const int c     = bc % C_;

    const float *X, *W, *bp;
    uint32_t* Yw;
    float scale;
    if (which == 0)      { X = query; W = wq; bp = bq; Yw = g_q + (size_t)bc * S_ * EW; scale = qscale; }
    else if (which == 1) { X = key;   W = wk; bp = bk; Yw = g_k + (size_t)bc * S_ * EW; scale = 1.0f; }
    else                 { X = value; W = wv; bp = bv; Yw = g_v + (size_t)bc * E_ * SP_; scale = 1.0f; }
    X  += (size_t)bc * S_ * E_;
    W  += (size_t)c  * E_ * E_;
    bp += (size_t)c  * E_;

    const int m0 = blockIdx.x * 128;
    const int n0 = blockIdx.y * 128;
    const int t  = threadIdx.x;
    const int warp  = t >> 5;
    const int warpm = warp >> 2;
    const int warpn = warp & 3;
    const int lane  = t & 31;
    const int g = lane >> 2;
    const int q = lane & 3;

    const int arow  = (lane & 7) + (((lane >> 3) & 1) << 3);
    const int akadd = (lane >> 4) << 2;
    const uint32_t smbA = (uint32_t)__cvta_generic_to_shared(sA);
    const uint32_t aBase = smbA + (uint32_t)(arow * PA2 + akadd) * 4u;

    float acc[4][4][4];
    #pragma unroll
    for (int i = 0; i < 4; i++)
        #pragma unroll
        for (int j = 0; j < 4; j++)
            #pragma unroll
            for (int r = 0; r < 4; r++) acc[i][j][r] = 0.0f;

    #pragma unroll 1
    for (int k0 = 0; k0 < E_; k0 += 128) {
        // A tile: 128 rows x 128 elems (4096 float4, 16/thread)
        #pragma unroll
        for (int i = 0; i < 16; i++) {
            const int idx = t + 256 * i;
            const int row = idx >> 5, c4 = idx & 31;
            *(uint2*)&sA[row * PA2 + c4 * 2] =
                pk4(*(const float4*)&X[(size_t)(m0 + row) * E_ + k0 + 4 * c4]);
        }
        // B tile: 128 k x 128 n as [kpair][n] (64 kp x 32 uint4, 8/thread)
        #pragma unroll
        for (int i = 0; i < 8; i++) {
            const int idx = t + 256 * i;
            const int kp = idx >> 5, n4 = (idx & 31) * 4;
            const float4 w0 = *(const float4*)&W[(size_t)(k0 + 2 * kp)     * E_ + n0 + n4];
            const float4 w1 = *(const float4*)&W[(size_t)(k0 + 2 * kp + 1) * E_ + n0 + n4];
            uint4 u;
            u.x = pk2(w0.x, w1.x); u.y = pk2(w0.y, w1.y);
            u.z = pk2(w0.z, w1.z); u.w = pk2(w0.w, w1.w);
            *(uint4*)&sB[kp * PBP + n4] = u;
        }
        __syncthreads();

        #pragma unroll
        for (int kkp = 0; kkp < 64; kkp += 8) {
            uint32_t a[4][4], b[4][2];
            #pragma unroll
            for (int mt = 0; mt < 4; mt++)
                ldsm4(a[mt], aBase + (uint32_t)((warpm * 64 + mt * 16) * PA2 + kkp) * 4u);
            #pragma unroll
            for (int nt = 0; nt < 4; nt++) {
                const int n = warpn * 32 + nt * 8 + g;
                b[nt][0] = sB[(kkp + q) * PBP + n];
                b[nt][1] = sB[(kkp + q + 4) * PBP + n];
            }
            #pragma unroll
            for (int mt = 0; mt < 4; mt++)
                #pragma unroll
                for (int nt = 0; nt < 4; nt++)
                    mma16(acc[mt][nt], a[mt], b[nt]);
        }
        __syncthreads();
    }

    if (which != 2) {
        #pragma unroll
        for (int nt = 0; nt < 4; nt++) {
            const int col = n0 + warpn * 32 + nt * 8 + 2 * q;
            const float b0v = bp[col], b1v = bp[col + 1];
            #pragma unroll
            for (int mt = 0; mt < 4; mt++) {
                const int row = m0 + warpm * 64 + mt * 16 + g;
                const float v00 = fmaxf(acc[mt][nt][0] + b0v, 0.0f) * scale;
                const float v01 = fmaxf(acc[mt][nt][1] + b1v, 0.0f) * scale;
                const float v10 = fmaxf(acc[mt][nt][2] + b0v, 0.0f) * scale;
                const float v11 = fmaxf(acc[mt][nt][3] + b1v, 0.0f) * scale;
                const int cw = (n0 >> 1) + warpn * 16 + nt * 4 + q;
                Yw[(size_t)row * EW + cw]       = pk2(v00, v01);
                Yw[(size_t)(row + 8) * EW + cw] = pk2(v10, v11);
            }
        }
    } else {
        #pragma unroll
        for (int nt = 0; nt < 4; nt++) {
            const int col = n0 + warpn * 32 + nt * 8 + 2 * q;
            const float b0v = bp[col], b1v = bp[col + 1];
            #pragma unroll
            for (int mt = 0; mt < 4; mt++) {
                const float v00 = fmaxf(acc[mt][nt][0] + b0v, 0.0f);
                const float v01 = fmaxf(acc[mt][nt][1] + b1v, 0.0f);
                const float v10 = fmaxf(acc[mt][nt][2] + b0v, 0.0f);
                const float v11 = fmaxf(acc[mt][nt][3] + b1v, 0.0f);
                const float p00 = __shfl_xor_sync(0xFFFFFFFFu, v00, 4);
                const float p01 = __shfl_xor_sync(0xFFFFFFFFu, v01, 4);
                const float p10 = __shfl_xor_sync(0xFFFFFFFFu, v10, 4);
                const float p11 = __shfl_xor_sync(0xFFFFFFFFu, v11, 4);
                if ((g & 1) == 0) {
                    const int lcol = warpn * 32 + nt * 8 + 2 * q;
                    const int lsp  = (warpm * 64 + mt * 16 + g) >> 1;
                    sT[lcol * PT + lsp]           = pk2(v00, p00);
                    sT[(lcol + 1) * PT + lsp]     = pk2(v01, p01);
                    sT[lcol * PT + lsp + 4]       = pk2(v10, p10);
                    sT[(lcol + 1) * PT + lsp + 4] = pk2(v11, p11);
                }
            }
        }
        __syncthreads();
        const int spb = m0 >> 1;
        #pragma unroll
        for (int i = 0; i < 8; i++) {
            const int o = t + 256 * i;
            const int col = o >> 4, j = o & 15;
            *(uint4*)&Yw[(size_t)(n0 + col) * SP_ + spb + j * 4] =
                *(uint4*)&sT[col * PT + j * 4];
        }
    }
}

// ---------------------------------------------------------------------------
// Attention — EXACT R16 best (140.4 us): 4 double-size chunks per phase,
// 2-stage buffering, 64 q-rows/CTA, 512 threads (2m x 8n).
// ---------------------------------------------------------------------------
#define PQF 132   // sQ pitch
#define PKC 36    // sK chunk pitch (32 words + 4)
#define SPP 260   // sS pitch
#define PVT 68    // sV chunk pitch (64 words + 4)

#define OFF_SQ 0             // 64*132 = 8448
#define OFF_K  8448          // 2 x 18432 -> ends 45312
#define KSTR   18432
#define OFF_SS 0             // 64*260 = 16640 (overlay)
#define OFF_V  16640         // 2 x 17408 -> ends 51456
#define VSTR   17408
#define OFF_RD 51456         // 1024 floats
#define ATT_WORDS 52480      // 209920 B

__global__ __launch_bounds__(512, 1) void attn_kernel(float* __restrict__ out)
{
    extern __shared__ uint32_t smu[];
    uint32_t* sQ = smu + OFF_SQ;
    uint32_t* sS = smu + OFF_SS;
    float* sRedM = (float*)(smu + OFF_RD);         // [64 rows][8 wn]
    float* sRedS = (float*)(smu + OFF_RD + 512);

    const uint32_t smb = (uint32_t)__cvta_generic_to_shared(smu);

    const int bc = blockIdx.y;
    const int q0 = blockIdx.x * 64;
    const uint32_t* Qw = g_q + (size_t)bc * S_ * EW;
    const uint32_t* Kw = g_k + (size_t)bc * S_ * EW;
    const uint32_t* Vw = g_v + (size_t)bc * E_ * SP_;
    float*          O  = out + (size_t)bc * S_ * E_;

    const int t    = threadIdx.x;
    const int warp = t >> 5;
    const int wm   = warp >> 3;
    const int wn   = warp & 7;
    const int lane = t & 31;
    const int g = lane >> 2;
    const int q = lane & 3;

    const int arow  = (lane & 7) + (((lane >> 3) & 1) << 3);
    const int akadd = (lane >> 4) << 2;
    const int brow  = (lane & 7) + ((lane >> 4) << 3);
    const int bkadd = ((lane >> 3) & 1) << 2;

    const uint32_t aQbase = smb + (uint32_t)(OFF_SQ + (wm * 32 + arow) * PQF + akadd) * 4u;
    const uint32_t aSbase = smb + (uint32_t)(OFF_SS + (wm * 32 + arow) * SPP + akadd) * 4u;
    const uint32_t bKoff  = (uint32_t)(brow * PKC + bkadd) * 4u;
    const uint32_t bVoff  = (uint32_t)(brow * PVT + bkadd) * 4u;

    // ---- issue K chunk 0 (512 rows x 32 words) ---------------------------
    {
        #pragma unroll
        for (int i = 0; i < 8; i++) {
            const int o = t + 512 * i;
            const int s = o >> 3, jj = o & 7;
            cpa16(smb + (uint32_t)(OFF_K + s * PKC + jj * 4) * 4u,
                  Kw + (size_t)s * EW + jj * 4);
        }
        CP_COMMIT();
    }

    // ---- stage whole Q tile (64 x 128 words) -----------------------------
    #pragma unroll
    for (int i = 0; i < 4; i++) {
        const int o = t + 512 * i;
        const int row = o >> 5, j = o & 31;
        *(uint4*)&sQ[row * PQF + j * 4] =
            *(const uint4*)&Qw[(size_t)(q0 + row) * EW + j * 4];
    }

    // ---------------- Phase 1: scores = Q K^T (4 chunks of 64 e) ----------
    float acc[2][8][4];
    #pragma unroll
    for (int mt = 0; mt < 2; mt++)
        #pragma unroll
        for (int nt = 0; nt < 8; nt++)
            #pragma unroll
            for (int r = 0; r < 4; r++) acc[mt][nt][r] = 0.0f;

    #pragma unroll 1
    for (int cch = 0; cch < 4; cch++) {
        CP_WAIT0();
        __syncthreads();
        if (cch < 3) {
            const uint32_t dst = smb + (uint32_t)(OFF_K + ((cch + 1) & 1) * KSTR) * 4u;
            const int ecp = (cch + 1) * 32;
            #pragma unroll
            for (int i = 0; i < 8; i++) {
                const int o = t + 512 * i;
                const int s = o >> 3, jj = o & 7;
                cpa16(dst + (uint32_t)(s * PKC + jj * 4) * 4u,
                      Kw + (size_t)s * EW + ecp + jj * 4);
            }
            CP_COMMIT();
        }
        const uint32_t bufK = smb + (uint32_t)(OFF_K + (cch & 1) * KSTR) * 4u;
        const int ecp = cch * 32;
        #pragma unroll
        for (int kkp = 0; kkp < 32; kkp += 8) {
            uint32_t a[2][4], b[8][2];
            #pragma unroll
            for (int mt = 0; mt < 2; mt++)
                ldsm4(a[mt], aQbase + (uint32_t)(mt * 16 * PQF + ecp + kkp) * 4u);
            #pragma unroll
            for (int nt2 = 0; nt2 < 8; nt2 += 2) {
                uint32_t r[4];
                ldsm4(r, bufK + (uint32_t)((wn * 64 + nt2 * 8) * PKC + kkp) * 4u + bKoff);
                b[nt2][0] = r[0]; b[nt2][1] = r[1];
                b[nt2 + 1][0] = r[2]; b[nt2 + 1][1] = r[3];
            }
            #pragma unroll
            for (int mt = 0; mt < 2; mt++)
                #pragma unroll
                for (int nt = 0; nt < 8; nt++)
                    mma16(acc[mt][nt], a[mt], b[nt]);
        }
    }

    // ---------------- Softmax (fp32 on fragments, 2-round) -----------------
    float rmax[4], rinv[4];
    #pragma unroll
    for (int mt = 0; mt < 2; mt++)
        #pragma unroll
        for (int h = 0; h < 2; h++) {
            float m = -1e30f;
            #pragma unroll
            for (int nt = 0; nt < 8; nt++) {
                m = fmaxf(m, acc[mt][nt][2 * h]);
                m = fmaxf(m, acc[mt][nt][2 * h + 1]);
            }
            m = fmaxf(m, __shfl_xor_sync(0xFFFFFFFFu, m, 1));
            m = fmaxf(m, __shfl_xor_sync(0xFFFFFFFFu, m, 2));
            rmax[mt * 2 + h] = m;
        }
    __syncthreads();   // all phase-1 K/Q smem reads done — overlays now safe

    // ---- issue V chunk 0 (256 f x 64 sp-words) — overlaps softmax --------
    {
        #pragma unroll
        for (int i = 0; i < 8; i++) {
            const int o = t + 512 * i;
            const int f = o >> 4, jj = o & 15;
            cpa16(smb + (uint32_t)(OFF_V + f * PVT + jj * 4) * 4u,
                  Vw + (size_t)f * SP_ + jj * 4);
        }
        CP_COMMIT();
    }

    if (q == 0) {
        #pragma unroll
        for (int mt = 0; mt < 2; mt++)
            #pragma unroll
            for (int h = 0; h < 2; h++)
                sRedM[(wm * 32 + mt * 16 + h * 8 + g) * 8 + wn] = rmax[mt * 2 + h];
    }
    __syncthreads();
    #pragma unroll
    for (int s = 0; s < 4; s++) {
        const int row = wm * 32 + (s >> 1) * 16 + (s & 1) * 8 + g;
        float m = sRedM[row * 8];
        #pragma unroll
        for (int w = 1; w < 8; w++) m = fmaxf(m, sRedM[row * 8 + w]);
        rmax[s] = m;
    }

    #pragma unroll
    for (int mt = 0; mt < 2; mt++)
        #pragma unroll
        for (int h = 0; h < 2; h++) {
            float s = 0.0f;
            #pragma unroll
            for (int nt = 0; nt < 8; nt++) {
                float p0 = __expf(acc[mt][nt][2 * h]     - rmax[mt * 2 + h]);
                float p1 = __expf(acc[mt][nt][2 * h + 1] - rmax[mt * 2 + h]);
                acc[mt][nt][2 * h]     = p0;
                acc[mt][nt][2 * h + 1] = p1;
                s += p0 + p1;
            }
            s += __shfl_xor_sync(0xFFFFFFFFu, s, 1);
            s += __shfl_xor_sync(0xFFFFFFFFu, s, 2);
            if (q == 0) sRedS[(wm * 32 + mt * 16 + h * 8 + g) * 8 + wn] = s;
        }
    __syncthreads();
    #pragma unroll
    for (int s = 0; s < 4; s++) {
        const int row = wm * 32 + (s >> 1) * 16 + (s & 1) * 8 + g;
        float sum = 0.0f;
        #pragma unroll
        for (int w = 0; w < 8; w++) sum += sRedS[row * 8 + w];
        rinv[s] = 1.0f / sum;
    }

    // Store unnormalized P (bf16 pairs) to sS
    #pragma unroll
    for (int mt = 0; mt < 2; mt++)
        #pragma unroll
        for (int h = 0; h < 2; h++) {
            const int row = wm * 32 + mt * 16 + h * 8 + g;
            #pragma unroll
            for (int nt = 0; nt < 8; nt++)
                sS[row * SPP + wn * 32 + nt * 4 + q] =
                    pk2(acc[mt][nt][2 * h], acc[mt][nt][2 * h + 1]);
        }

    // ---------------- Phase 2: out = P V (4 chunks of 128 s) ---------------
    float acc2[2][4][4];
    #pragma unroll
    for (int mt = 0; mt < 2; mt++)
        #pragma unroll
        for (int nt = 0; nt < 4; nt++)
            #pragma unroll
            for (int r = 0; r < 4; r++) acc2[mt][nt][r] = 0.0f;

    #pragma unroll 1
    for (int cch = 0; cch < 4; cch++) {
        CP_WAIT0();
        __syncthreads();           // V chunk ready + (first iter) P visible
        if (cch < 3) {
            const uint32_t dst = smb + (uint32_t)(OFF_V + ((cch + 1) & 1) * VSTR) * 4u;
            const int spb = (cch + 1) * 64;
            #pragma unroll
            for (int i = 0; i < 8; i++) {
                const int o = t + 512 * i;
                const int f = o >> 4, jj = o & 15;
                cpa16(dst + (uint32_t)(f * PVT + jj * 4) * 4u,
                      Vw + (size_t)f * SP_ + spb + jj * 4);
            }
            CP_COMMIT();
        }
        const uint32_t bufV = smb + (uint32_t)(OFF_V + (cch & 1) * VSTR) * 4u;
        const int ktp = cch * 64;
        #pragma unroll
        for (int kkp = 0; kkp < 64; kkp += 8) {
            uint32_t a[2][4], b[4][2];
            #pragma unroll
            for (int mt = 0; mt < 2; mt++)
                ldsm4(a[mt], aSbase + (uint32_t)(mt * 16 * SPP + ktp + kkp) * 4u);
            #pragma unroll
            for (int nt2 = 0; nt2 < 4; nt2 += 2) {
                uint32_t r[4];
                ldsm4(r, bufV + (uint32_t)((wn * 32 + nt2 * 8) * PVT + kkp) * 4u + bVoff);
                b[nt2][0] = r[0]; b[nt2][1] = r[1];
                b[nt2 + 1][0] = r[2]; b[nt2 + 1][1] = r[3];
            }
            #pragma unroll
            for (int mt = 0; mt < 2; mt++)
                #pragma unroll
                for (int nt = 0; nt < 4; nt++)
                    mma16(acc2[mt][nt], a[mt], b[nt]);
        }
    }

    // Epilogue: normalize + store fp32
    #pragma unroll
    for (int mt = 0; mt < 2; mt++)
        #pragma unroll
        for (int h = 0; h < 2; h++) {
            const int row = q0 + wm * 32 + mt * 16 + h * 8 + g;
            const float inv = rinv[mt * 2 + h];
            #pragma unroll
            for (int nt = 0; nt < 4; nt++) {
                const int col = wn * 32 + nt * 8 + 2 * q;
                float2 v;
                v.x = acc2[mt][nt][2 * h]     * inv;
                v.y = acc2[mt][nt][2 * h + 1] * inv;
                *(float2*)&O[(size_t)row * E_ + col] = v;
            }
        }
}

// ---------------------------------------------------------------------------
extern "C" void kernel_launch(void* const* d_in, const int* in_sizes, int n_in,
                              void* d_out, int out_size)
{
    const float* query = (const float*)d_in[0];
    const float* key   = (const float*)d_in[1];
    const float* value = (const float*)d_in[2];
    const float* wq    = (const float*)d_in[3];
    const float* wk    = (const float*)d_in[4];
    const float* wv    = (const float*)d_in[5];
    const float* bq    = (const float*)d_in[6];
    const float* bk    = (const float*)d_in[7];
    const float* bv    = (const float*)d_in[8];
    float* out = (float*)d_out;

    const float qscale = 1.0f / sqrtf((float)E_);

    const int pj_smem = PJ_WORDS * 4;
    cudaFuncSetAttribute(proj_kernel, cudaFuncAttributeMaxDynamicSharedMemorySize,
                         pj_smem);
    dim3 pgrid(S_ / 128, E_ / 128, 3 * BC_);
    proj_kernel<<<pgrid, 256, pj_smem>>>(query, key, value, wq, wk, wv,
                                         bq, bk, bv, qscale);

    const size_t smem = (size_t)ATT_WORDS * sizeof(uint32_t);
    cudaFuncSetAttribute(attn_kernel, cudaFuncAttributeMaxDynamicSharedMemorySize,
                         (int)smem);
    attn_kernel<<<dim3(S_ / 64, BC_), 512, smem>>>(out);
}